// round 15
// baseline (speedup 1.0000x reference)
#include <cuda_runtime.h>
#include <cuda_fp16.h>
#include <cstdint>
#include <math.h>

#define TT 2048
#define DD 2048
#define HH 16
#define DHD 128
#define FFD 8192

// ---------------- scratch (device globals) ---------------------------------
__device__ __align__(256) __half g_xn [TT * DD];
__device__ __align__(256) __half g_qh[TT * DD], g_kh[TT * DD], g_vh[TT * DD];
__device__ __align__(256) __half g_ctx[TT * DD];
__device__ __align__(256) __half g_ffh[TT * FFD];
__device__ __align__(256) __half g_wqh[DD * DD];
__device__ __align__(256) __half g_wkh[DD * DD];
__device__ __align__(256) __half g_wvh[DD * DD];
__device__ __align__(256) __half g_woh[DD * DD];
__device__ __align__(256) __half g_w1h[DD * FFD];
__device__ __align__(256) __half g_w2h[FFD * DD];
__device__ __align__(256) float2 g_rope[TT * 32];

// ---------------- PTX helpers ----------------------------------------------
__device__ __forceinline__ uint32_t smem_u32(const void* p) {
    uint32_t a;
    asm("{ .reg .u64 t; cvta.to.shared.u64 t, %1; cvt.u32.u64 %0, t; }"
        : "=r"(a) : "l"(p));
    return a;
}
__device__ __forceinline__ uint32_t h2_as_u32(__half2 h) {
    union { __half2 h2; uint32_t u; } cvt;
    cvt.h2 = h;
    return cvt.u;
}
__device__ __forceinline__ void cpa16(uint32_t dst, const void* src) {
    asm volatile("cp.async.cg.shared.global [%0], [%1], 16;"
                 :: "r"(dst), "l"(src));
}
#define CPA_COMMIT() asm volatile("cp.async.commit_group;" ::: "memory")
#define CPA_WAIT2()  asm volatile("cp.async.wait_group 2;" ::: "memory")
#define CPA_WAIT1()  asm volatile("cp.async.wait_group 1;" ::: "memory")
#define CPA_WAIT0()  asm volatile("cp.async.wait_group 0;" ::: "memory")

__device__ __forceinline__ void ldsm4(uint32_t& r0, uint32_t& r1,
                                      uint32_t& r2, uint32_t& r3, uint32_t a) {
    asm volatile("ldmatrix.sync.aligned.m8n8.x4.shared.b16 {%0,%1,%2,%3}, [%4];"
                 : "=r"(r0), "=r"(r1), "=r"(r2), "=r"(r3) : "r"(a));
}
__device__ __forceinline__ void ldsm4t(uint32_t& r0, uint32_t& r1,
                                       uint32_t& r2, uint32_t& r3, uint32_t a) {
    asm volatile("ldmatrix.sync.aligned.m8n8.x4.trans.shared.b16 {%0,%1,%2,%3}, [%4];"
                 : "=r"(r0), "=r"(r1), "=r"(r2), "=r"(r3) : "r"(a));
}
__device__ __forceinline__ void mma16816(float* c, const uint32_t* a,
                                         const uint32_t* b) {
    asm volatile(
        "mma.sync.aligned.m16n8k16.row.col.f32.f16.f16.f32 "
        "{%0,%1,%2,%3}, {%4,%5,%6,%7}, {%8,%9}, {%0,%1,%2,%3};"
        : "+f"(c[0]), "+f"(c[1]), "+f"(c[2]), "+f"(c[3])
        : "r"(a[0]), "r"(a[1]), "r"(a[2]), "r"(a[3]), "r"(b[0]), "r"(b[1]));
}

__device__ __forceinline__ float gelu_tanh(float v) {
    float u = 0.7978845608028654f * (v + 0.044715f * v * v * v);
    return 0.5f * v * (1.0f + tanhf(u));
}

// ---------------- merged prep: LN + rope table + weight convert ------------
__global__ void prep_all(const float* __restrict__ x,
                         const float* __restrict__ scale,
                         const float* __restrict__ offset,
                         const float* __restrict__ wq, const float* __restrict__ wk,
                         const float* __restrict__ wv, const float* __restrict__ wo,
                         const float* __restrict__ w1, const float* __restrict__ w2,
                         __half* __restrict__ xn, float2* __restrict__ rope,
                         __half* __restrict__ wqh, __half* __restrict__ wkh,
                         __half* __restrict__ wvh, __half* __restrict__ woh,
                         __half* __restrict__ w1h, __half* __restrict__ w2h) {
    int b = blockIdx.x, tid = threadIdx.x;
    __shared__ float red[256];
    if (b < TT) {
        const float* xr = x + (size_t)b * DD;
        float vals[8];
        float s = 0.f;
#pragma unroll
        for (int i = 0; i < 8; i++) { vals[i] = xr[tid + i * 256]; s += vals[i]; }
        red[tid] = s; __syncthreads();
#pragma unroll
        for (int off = 128; off > 0; off >>= 1) {
            if (tid < off) red[tid] += red[tid + off];
            __syncthreads();
        }
        float mean = red[0] * (1.0f / DD);
        __syncthreads();
        float vs = 0.f;
#pragma unroll
        for (int i = 0; i < 8; i++) { float d = vals[i] - mean; vs += d * d; }
        red[tid] = vs; __syncthreads();
#pragma unroll
        for (int off = 128; off > 0; off >>= 1) {
            if (tid < off) red[tid] += red[tid + off];
            __syncthreads();
        }
        float var = red[0] * (1.0f / DD);
        float inv = rsqrtf(var + 1e-5f);
#pragma unroll
        for (int i = 0; i < 8; i++) {
            int c = tid + i * 256;
            float y = scale[c] * inv * (vals[i] - mean) + offset[c];
            xn[(size_t)b * DD + c] = __float2half(y);
        }
    } else if (b < TT + 256) {
        int idx = (b - TT) * 256 + tid;
        int j = idx & 31, t = idx >> 5;
        float inv = (float)pow(10000.0, -(double)(2 * j) / 64.0);
        float ang = (float)t * inv;
        rope[idx] = make_float2(cosf(ang), sinf(ang));
    } else {
        const long long NV = 12LL * 1024 * 1024;
        long long stride = 1536LL * 256;
        for (long long i = (long long)(b - TT - 256) * 256 + tid;
             i < NV; i += stride) {
            const float* src; __half* dst; long long l;
            if (i < 4LL * 1024 * 1024) {
                int seg = (int)(i >> 20);
                l = i & 0xFFFFF;
                src = seg == 0 ? wq : (seg == 1 ? wk : (seg == 2 ? wv : wo));
                dst = seg == 0 ? wqh : (seg == 1 ? wkh : (seg == 2 ? wvh : woh));
            } else if (i < 8LL * 1024 * 1024) {
                l = i - 4LL * 1024 * 1024; src = w1; dst = w1h;
            } else {
                l = i - 8LL * 1024 * 1024; src = w2; dst = w2h;
            }
            float4 v = ((const float4*)src)[l];
            uint2 o;
            o.x = h2_as_u32(__floats2half2_rn(v.x, v.y));
            o.y = h2_as_u32(__floats2half2_rn(v.z, v.w));
            ((uint2*)dst)[l] = o;
        }
    }
}

// ---------------- HMMA GEMM: 128x256 tile, 8 warps (64x64/warp), K64 -------
// 1 CTA/SM, 255 regs, explicit fragment double-buffering (CUTLASS shape).
// mode 1: outH0 = fp16(gelu(D + bias))                       (FF1)
// mode 7: merged QKV — bx>>3 selects rope/rope/plain
// mode 9: WO+FF2 concat-K: chunks 0..31 = ctx@woh, 32..159 = ffh@w2h;
//         epilogue outF = D + res(x) + bias(b2)
#define ARB 144                      // A smem row bytes (64 halfs + 16 pad)
#define BRB 528                      // B smem row bytes (256 halfs + 16 pad)
#define ATILEB (128 * ARB)           // 18432
#define BTILEB (64 * BRB)            // 33792
#define STAGEB (ATILEB + BTILEB)     // 52224
#define NSTAGE 4
#define GSMEM (NSTAGE * STAGEB)      // 208896

__global__ void __launch_bounds__(256, 1) gemm_hmma(
    const __half* __restrict__ A,
    const __half* __restrict__ B0, const __half* __restrict__ B1,
    const __half* __restrict__ B2,
    int M, int N, int K,
    float* __restrict__ outF,
    __half* __restrict__ outH0, __half* __restrict__ outH1,
    __half* __restrict__ outH2,
    const float* __restrict__ bias, const float* __restrict__ res,
    const float2* __restrict__ rope, int mode) {
    extern __shared__ char smem[];
    const uint32_t sb = smem_u32(smem);

    const int tid = threadIdx.x;
    const int wid = tid >> 5, lane = tid & 31;
    const int wm = wid >> 2, wn = wid & 3;        // 2 x 4 warps, 64x64 each

    int bx = blockIdx.x;
    const __half* Bsel = B0;
    __half* outH = outH0;
    int em = mode;
    const int NN = N;
    if (mode == 7) {
        int which = bx >> 3;
        bx &= 7;
        Bsel = which == 0 ? B0 : (which == 1 ? B1 : B2);
        outH = which == 0 ? outH0 : (which == 1 ? outH1 : outH2);
        em   = which < 2 ? 4 : 6;
    }
    const int m0 = blockIdx.y << 7, n0 = bx << 8;

    // A copy: thread t -> row t>>1, half (t&1): 4x16B
    const int ar = tid >> 1, aq = tid & 1;
    // B copy: thread t -> row t>>2, quarter (t&3): 8x16B
    const int bre = tid >> 2, bq = tid & 3;

    const uint32_t a_off = (uint32_t)(wm * 64 + (lane & 15)) * ARB + ((lane >> 4) << 4);
    const uint32_t b_toff = (uint32_t)((lane & 7) + ((lane >> 3) & 1) * 8) * BRB
                          + (uint32_t)(wn * 128) + (((lane >> 3) >> 1) << 4);

    float acc[4][8][4];
#pragma unroll
    for (int i = 0; i < 4; i++)
#pragma unroll
        for (int j = 0; j < 8; j++)
#pragma unroll
            for (int r = 0; r < 4; r++) acc[i][j][r] = 0.f;

    const int nch = (mode == 9) ? ((DD + FFD) >> 6) : (K >> 6);
    const __half* Ab = A + (size_t)(m0 + ar) * K + aq * 32;
    const __half* Bb = Bsel + (size_t)bre * NN + n0 + bq * 64;

#define PREFETCH_G(ci) do {                                                   \
        if ((ci) < nch) {                                                     \
            const uint32_t st = sb + ((ci) % NSTAGE) * STAGEB;                \
            int kc = (ci) << 6;                                               \
            _Pragma("unroll")                                                 \
            for (int u = 0; u < 4; u++)                                       \
                cpa16(st + ar * ARB + aq * 64 + u * 16, Ab + kc + u * 8);     \
            size_t bk = (size_t)kc * NN;                                      \
            _Pragma("unroll")                                                 \
            for (int u = 0; u < 8; u++)                                       \
                cpa16(st + ATILEB + bre * BRB + bq * 128 + u * 16,            \
                      Bb + bk + u * 8);                                       \
        }                                                                     \
        CPA_COMMIT();                                                         \
    } while (0)

    PREFETCH_G(0);
    PREFETCH_G(1);
    PREFETCH_G(2);

    for (int i = 0; i < nch; i++) {
        CPA_WAIT2();              // chunk i landed (2 newer groups may pend)
        __syncthreads();          // all warps finished stage (i-1)%4
        if (mode == 9 && i + 3 == (DD >> 6)) {
            Ab = g_ffh + (size_t)(m0 + ar) * FFD + aq * 32 - DD;
            Bb = g_w2h + (size_t)bre * DD + n0 + bq * 64 - (size_t)DD * DD;
        }
        PREFETCH_G(i + 3);        // overwrites stage (i-1)%4 — safe

        const uint32_t sA = sb + (i % NSTAGE) * STAGEB;
        const uint32_t sB = sA + ATILEB;

        uint32_t af[2][4][4], bf[2][8][2];
        // load ks=0 fragments into buffer 0
#pragma unroll
        for (int fi = 0; fi < 4; fi++)
            ldsm4(af[0][fi][0], af[0][fi][1], af[0][fi][2], af[0][fi][3],
                  sA + a_off + fi * 16 * ARB);
#pragma unroll
        for (int j2 = 0; j2 < 4; j2++) {
            uint32_t r0, r1, r2, r3;
            ldsm4t(r0, r1, r2, r3, sB + b_toff + j2 * 32);
            bf[0][j2 * 2][0] = r0; bf[0][j2 * 2][1] = r1;
            bf[0][j2 * 2 + 1][0] = r2; bf[0][j2 * 2 + 1][1] = r3;
        }
#pragma unroll
        for (int ks = 0; ks < 4; ks++) {
            const int cur = ks & 1, nxt = cur ^ 1;
            if (ks < 3) {
#pragma unroll
                for (int fi = 0; fi < 4; fi++)
                    ldsm4(af[nxt][fi][0], af[nxt][fi][1],
                          af[nxt][fi][2], af[nxt][fi][3],
                          sA + a_off + fi * 16 * ARB + (ks + 1) * 32);
#pragma unroll
                for (int j2 = 0; j2 < 4; j2++) {
                    uint32_t r0, r1, r2, r3;
                    ldsm4t(r0, r1, r2, r3,
                           sB + b_toff + (ks + 1) * 16 * BRB + j2 * 32);
                    bf[nxt][j2 * 2][0] = r0; bf[nxt][j2 * 2][1] = r1;
                    bf[nxt][j2 * 2 + 1][0] = r2; bf[nxt][j2 * 2 + 1][1] = r3;
                }
            }
#pragma unroll
            for (int fi = 0; fi < 4; fi++)
#pragma unroll
                for (int j = 0; j < 8; j++)
                    mma16816(acc[fi][j], af[cur][fi], bf[cur][j]);
        }
    }
#undef PREFETCH_G

    const int r_base = m0 + wm * 64 + (lane >> 2);
    const int c_base = n0 + wn * 64 + (lane & 3) * 2;
#pragma unroll
    for (int fi = 0; fi < 4; fi++) {
#pragma unroll
        for (int j = 0; j < 8; j++) {
            int col = c_base + j * 8;
#pragma unroll
            for (int half_ = 0; half_ < 2; half_++) {
                int r = r_base + fi * 16 + half_ * 8;
                float v0 = acc[fi][j][half_ * 2 + 0];
                float v1 = acc[fi][j][half_ * 2 + 1];
                size_t o = (size_t)r * NN + col;
                if (em == 1) {
                    *(__half2*)&outH[o] = __floats2half2_rn(
                        gelu_tanh(v0 + bias[col]), gelu_tanh(v1 + bias[col + 1]));
                } else if (em == 4) {
                    int hcol = col & 127;
                    if (hcol < 64) {
                        float2 cs = rope[r * 32 + (hcol >> 1)];
                        *(__half2*)&outH[o] = __floats2half2_rn(
                            v0 * cs.x - v1 * cs.y, v1 * cs.x + v0 * cs.y);
                    } else {
                        *(__half2*)&outH[o] = __floats2half2_rn(v0, v1);
                    }
                } else if (em == 6) {
                    *(__half2*)&outH[o] = __floats2half2_rn(v0, v1);
                } else {  // em == 9: out = acc + x + b2
                    float2 rr = *(const float2*)&res[o];
                    float2 ov = make_float2(v0 + rr.x + bias[col],
                                            v1 + rr.y + bias[col + 1]);
                    *(float2*)&outF[o] = ov;
                }
            }
        }
    }
}

// ---------------- Flash attention: Br=64, 4 warps, 2 CTA/SM ----------------
#define KRB 272
#define KSTG (64 * KRB)
#define SSTG (2 * KSTG)
#define ASMEM (2 * SSTG)

__global__ void __launch_bounds__(128, 2) attn_mma(
    const __half* __restrict__ qh, const __half* __restrict__ kh,
    const __half* __restrict__ vh, __half* __restrict__ ctx) {
    extern __shared__ char smem[];
    const uint32_t sb = smem_u32(smem);
    const int tid = threadIdx.x, w = tid >> 5, lane = tid & 31;
    const int qt = gridDim.x - 1 - blockIdx.x;     // LPT: longest first
    const int h = blockIdx.y;
    const int q0 = qt * 64;
    const int hbase = h * DHD;
    const int nkt = qt + 1;

#pragma unroll
    for (int p = 0; p < 8; p++) {
        int idx = tid + p * 128;
        int row = idx >> 4, c = idx & 15;
        cpa16(sb + row * KRB + c * 16,
              qh + (size_t)(q0 + row) * DD + hbase + c * 8);
    }
    CPA_COMMIT(); CPA_WAIT0(); __syncthreads();
    uint32_t qf[8][4];
    {
        uint32_t aoff = (uint32_t)(w * 16 + (lane & 15)) * KRB + ((lane >> 4) << 4);
#pragma unroll
        for (int ks = 0; ks < 8; ks++)
            ldsm4(qf[ks][0], qf[ks][1], qf[ks][2], qf[ks][3],
                  sb + aoff + ks * 32);
    }
    __syncthreads();

    float O[16][4];
#pragma unroll
    for (int j = 0; j < 16; j++)
#pragma unroll
        for (int r = 0; r < 4; r++) O[j][r] = 0.f;
    float m0 = -1e30f, m1 = -1e30f, l0 = 0.f, l1 = 0.f;

#define LOADKV(kt_) do {                                                      \
        int kv0 = (kt_) * 64;                                                 \
        uint32_t base = sb + ((kt_) & 1) * SSTG;                              \
        _Pragma("unroll")                                                     \
        for (int p = 0; p < 8; p++) {                                         \
            int idx = tid + p * 128;                                          \
            int row = idx >> 4, c = idx & 15;                                 \
            cpa16(base + row * KRB + c * 16,                                  \
                  kh + (size_t)(kv0 + row) * DD + hbase + c * 8);             \
        }                                                                     \
        _Pragma("unroll")                                                     \
        for (int p = 0; p < 8; p++) {                                         \
            int idx = tid + p * 128;                                          \
            int row = idx >> 4, c = idx & 15;                                 \
            cpa16(base + KSTG + row * KRB + c * 16,                           \
                  vh + (size_t)(kv0 + row) * DD + hbase + c * 8);             \
        }                                                                     \
        CPA_COMMIT();                                                         \
    } while (0)

    LOADKV(0);

    const float sm_scale = 0.08838834764831845f;
    const int r0g = q0 + w * 16 + (lane >> 2);

    for (int kt = 0; kt < nkt; kt++) {
        if (kt + 1 < nkt) { LOADKV(kt + 1); CPA_WAIT1(); }
        else { CPA_WAIT0(); }
        __syncthreads();

        const uint32_t cur = sb + (kt & 1) * SSTG;

        float S[8][4];
#pragma unroll
        for (int j = 0; j < 8; j++)
#pragma unroll
            for (int r = 0; r < 4; r++) S[j][r] = 0.f;
        {
            uint32_t bko = (uint32_t)((lane & 7) + ((lane >> 4) << 3)) * KRB
                         + (((lane >> 3) & 1) << 4);
#pragma unroll
            for (int j2 = 0; j2 < 4; j2++) {
                uint32_t bbase = cur + bko + j2 * 16 * KRB;
#pragma unroll
                for (int ks = 0; ks < 8; ks++) {
                    uint32_t r0, r1, r2, r3;
                    ldsm4(r0, r1, r2, r3, bbase + ks * 32);
                    uint32_t bb0[2] = {r0, r1};
                    mma16816(S[2 * j2], qf[ks], bb0);
                    uint32_t bb1[2] = {r2, r3};
                    mma16816(S[2 * j2 + 1], qf[ks], bb1);
                }
            }
        }

        int kv0 = kt * 64;
        bool msk = (kt == nkt - 1);
#pragma unroll
        for (int j = 0; j < 8; j++) {
            S[j][0] *= sm_scale; S[j][1] *= sm_scale;
            S[j][2] *= sm_scale; S[j][3] *= sm_scale;
            if (msk) {
                int c0 = kv0 + j * 8 + 2 * (lane & 3);
                if (c0 > r0g)     S[j][0] = -1e9f;
                if (c0 + 1 > r0g) S[j][1] = -1e9f;
                if (c0 > r0g + 8)     S[j][2] = -1e9f;
                if (c0 + 1 > r0g + 8) S[j][3] = -1e9f;
            }
        }

        float mx0 = -1e30f, mx1 = -1e30f;
#pragma unroll
        for (int j = 0; j < 8; j++) {
            mx0 = fmaxf(mx0, fmaxf(S[j][0], S[j][1]));
            mx1 = fmaxf(mx1, fmaxf(S[j][2], S[j][3]));
        }
        mx0 = fmaxf(mx0, __shfl_xor_sync(0xffffffffu, mx0, 1));
        mx0 = fmaxf(mx0, __shfl_xor_sync(0xffffffffu, mx0, 2));
        mx1 = fmaxf(mx1, __shfl_xor_sync(0xffffffffu, mx1, 1));
        mx1 = fmaxf(mx1, __shfl_xor_sync(0xffffffffu, mx1, 2));
        float m0n = fmaxf(m0, mx0), m1n = fmaxf(m1, mx1);
        float c0f = __expf(m0 - m0n), c1f = __expf(m1 - m1n);
        float s0 = 0.f, s1 = 0.f;
#pragma unroll
        for (int j = 0; j < 8; j++) {
            S[j][0] = __expf(S[j][0] - m0n);
            S[j][1] = __expf(S[j][1] - m0n);
            S[j][2] = __expf(S[j][2] - m1n);
            S[j][3] = __expf(S[j][3] - m1n);
            s0 += S[j][0] + S[j][1];
            s1 += S[j][2] + S[j][3];
        }
        s0 += __shfl_xor_sync(0xffffffffu, s0, 1);
        s0 += __shfl_xor_sync(0xffffffffu, s0, 2);
        s1 += __shfl_xor_sync(0xffffffffu, s1, 1);
        s1 += __shfl_xor_sync(0xffffffffu, s1, 2);
        l0 = l0 * c0f + s0;
        l1 = l1 * c1f + s1;
        m0 = m0n; m1 = m1n;
#pragma unroll
        for (int j = 0; j < 16; j++) {
            O[j][0] *= c0f; O[j][1] *= c0f;
            O[j][2] *= c1f; O[j][3] *= c1f;
        }

        {
            uint32_t vbase = cur + KSTG;
            uint32_t bvo = (uint32_t)((lane & 7) + ((lane >> 3) & 1) * 8) * KRB
                         + (((lane >> 3) >> 1) << 4);
#pragma unroll
            for (int kk = 0; kk < 4; kk++) {
                uint32_t pf[4];
                pf[0] = h2_as_u32(__floats2half2_rn(S[2 * kk][0], S[2 * kk][1]));
                pf[1] = h2_as_u32(__floats2half2_rn(S[2 * kk][2], S[2 * kk][3]));
                pf[2] = h2_as_u32(__floats2half2_rn(S[2 * kk + 1][0], S[2 * kk + 1][1]));
                pf[3] = h2_as_u32(__floats2half2_rn(S[2 * kk + 1][2], S[2 * kk + 1][3]));
#pragma unroll
                for (int j2 = 0; j2 < 8; j2++) {
                    uint32_t r0, r1, r2, r3;
                    ldsm4t(r0, r1, r2, r3,
                           vbase + bvo + kk * 16 * KRB + j2 * 32);
                    uint32_t bb0[2] = {r0, r1};
                    mma16816(O[2 * j2], pf, bb0);
                    uint32_t bb1[2] = {r2, r3};
                    mma16816(O[2 * j2 + 1], pf, bb1);
                }
            }
        }
        __syncthreads();
    }
#undef LOADKV

    float i0 = 1.f / l0, i1 = 1.f / l1;
    int row0 = q0 + w * 16 + (lane >> 2);
#pragma unroll
    for (int j = 0; j < 16; j++) {
        int col = hbase + j * 8 + 2 * (lane & 3);
        *(__half2*)(ctx + (size_t)row0 * DD + col) =
            __floats2half2_rn(O[j][0] * i0, O[j][1] * i0);
        *(__half2*)(ctx + (size_t)(row0 + 8) * DD + col) =
            __floats2half2_rn(O[j][2] * i1, O[j][3] * i1);
    }
}

// ---------------- launch ----------------------------------------------------
extern "C" void kernel_launch(void* const* d_in, const int* in_sizes, int n_in,
                              void* d_out, int out_size) {
    const float* x      = (const float*)d_in[0];
    const float* scale  = (const float*)d_in[2];
    const float* offset = (const float*)d_in[3];
    const float* wq     = (const float*)d_in[4];
    const float* wk     = (const float*)d_in[5];
    const float* wv     = (const float*)d_in[6];
    const float* wo     = (const float*)d_in[7];
    const float* w1     = (const float*)d_in[8];
    const float* b1     = (const float*)d_in[9];
    const float* w2     = (const float*)d_in[10];
    const float* b2     = (const float*)d_in[11];
    float* out = (float*)d_out;

    __half *xn, *ctx, *ffh, *wqh, *wkh, *wvh, *woh, *w1h, *w2h, *qh, *kh, *vh;
    float2* rope;
    cudaGetSymbolAddress((void**)&xn, g_xn);
    cudaGetSymbolAddress((void**)&qh, g_qh);
    cudaGetSymbolAddress((void**)&kh, g_kh);
    cudaGetSymbolAddress((void**)&vh, g_vh);
    cudaGetSymbolAddress((void**)&ctx, g_ctx);
    cudaGetSymbolAddress((void**)&ffh, g_ffh);
    cudaGetSymbolAddress((void**)&wqh, g_wqh);
    cudaGetSymbolAddress((void**)&wkh, g_wkh);
    cudaGetSymbolAddress((void**)&wvh, g_wvh);
    cudaGetSymbolAddress((void**)&woh, g_woh);
    cudaGetSymbolAddress((void**)&w1h, g_w1h);
    cudaGetSymbolAddress((void**)&w2h, g_w2h);
    cudaGetSymbolAddress((void**)&rope, g_rope);

    static cudaStream_t s2 = nullptr;
    static cudaEvent_t evPrep = nullptr, evFF1 = nullptr;
    if (s2 == nullptr) {
        cudaStreamCreateWithFlags(&s2, cudaStreamNonBlocking);
        cudaEventCreateWithFlags(&evPrep, cudaEventDisableTiming);
        cudaEventCreateWithFlags(&evFF1, cudaEventDisableTiming);
    }

    cudaFuncSetAttribute(attn_mma,
                         cudaFuncAttributeMaxDynamicSharedMemorySize, ASMEM);
    cudaFuncSetAttribute(gemm_hmma,
                         cudaFuncAttributeMaxDynamicSharedMemorySize, GSMEM);

    // prep (LN + rope + convert) on main stream
    prep_all<<<3840, 256>>>(x, scale, offset, wq, wk, wv, wo, w1, w2,
                            xn, rope, wqh, wkh, wvh, woh, w1h, w2h);
    cudaEventRecord(evPrep, 0);

    // FF1 on side stream (depends only on prep)
    cudaStreamWaitEvent(s2, evPrep, 0);
    gemm_hmma<<<dim3(FFD / 256, TT / 128), 256, GSMEM, s2>>>(
        xn, w1h, nullptr, nullptr, TT, FFD, DD,
        nullptr, ffh, nullptr, nullptr, b1, nullptr, nullptr, 1);
    cudaEventRecord(evFF1, s2);

    // QKV + attention on main stream (concurrent with FF1)
    gemm_hmma<<<dim3(24, TT / 128), 256, GSMEM>>>(
        xn, wqh, wkh, wvh, TT, DD, DD,
        nullptr, qh, kh, vh, nullptr, nullptr, rope, 7);
    attn_mma<<<dim3(TT / 64, HH), 128, ASMEM>>>(qh, kh, vh, ctx);

    // join, then fused WO + FF2 (concatenated K): out = ctx@wo + ffh@w2 + x + b2
    cudaStreamWaitEvent(0, evFF1, 0);
    gemm_hmma<<<dim3(DD / 256, TT / 128), 256, GSMEM>>>(
        ctx, woh, nullptr, nullptr, TT, DD, DD,
        out, nullptr, nullptr, nullptr, b2, x, nullptr, 9);
}

// round 16
// speedup vs baseline: 1.3848x; 1.3848x over previous
#include <cuda_runtime.h>
#include <cuda_fp16.h>
#include <cstdint>
#include <math.h>

#define TT 2048
#define DD 2048
#define HH 16
#define DHD 128
#define FFD 8192

// ---------------- scratch (device globals) ---------------------------------
__device__ __align__(256) __half g_xn [TT * DD];
__device__ __align__(256) __half g_qh[TT * DD], g_kh[TT * DD], g_vh[TT * DD];
__device__ __align__(256) __half g_ctx[TT * DD];
__device__ __align__(256) __half g_ffh[TT * FFD];
__device__ __align__(256) __half g_wqh[DD * DD];
__device__ __align__(256) __half g_wkh[DD * DD];
__device__ __align__(256) __half g_wvh[DD * DD];
__device__ __align__(256) __half g_woh[DD * DD];
__device__ __align__(256) __half g_w1h[DD * FFD];
__device__ __align__(256) __half g_w2h[FFD * DD];
__device__ __align__(256) float2 g_rope[TT * 32];

// ---------------- PTX helpers ----------------------------------------------
__device__ __forceinline__ uint32_t smem_u32(const void* p) {
    uint32_t a;
    asm("{ .reg .u64 t; cvta.to.shared.u64 t, %1; cvt.u32.u64 %0, t; }"
        : "=r"(a) : "l"(p));
    return a;
}
__device__ __forceinline__ uint32_t h2_as_u32(__half2 h) {
    union { __half2 h2; uint32_t u; } cvt;
    cvt.h2 = h;
    return cvt.u;
}
__device__ __forceinline__ void cpa16(uint32_t dst, const void* src) {
    asm volatile("cp.async.cg.shared.global [%0], [%1], 16;"
                 :: "r"(dst), "l"(src));
}
#define CPA_COMMIT() asm volatile("cp.async.commit_group;" ::: "memory")
#define CPA_WAIT1()  asm volatile("cp.async.wait_group 1;" ::: "memory")
#define CPA_WAIT0()  asm volatile("cp.async.wait_group 0;" ::: "memory")

__device__ __forceinline__ void ldsm4(uint32_t& r0, uint32_t& r1,
                                      uint32_t& r2, uint32_t& r3, uint32_t a) {
    asm volatile("ldmatrix.sync.aligned.m8n8.x4.shared.b16 {%0,%1,%2,%3}, [%4];"
                 : "=r"(r0), "=r"(r1), "=r"(r2), "=r"(r3) : "r"(a));
}
__device__ __forceinline__ void ldsm4t(uint32_t& r0, uint32_t& r1,
                                       uint32_t& r2, uint32_t& r3, uint32_t a) {
    asm volatile("ldmatrix.sync.aligned.m8n8.x4.trans.shared.b16 {%0,%1,%2,%3}, [%4];"
                 : "=r"(r0), "=r"(r1), "=r"(r2), "=r"(r3) : "r"(a));
}
__device__ __forceinline__ void mma16816(float* c, const uint32_t* a,
                                         const uint32_t* b) {
    asm volatile(
        "mma.sync.aligned.m16n8k16.row.col.f32.f16.f16.f32 "
        "{%0,%1,%2,%3}, {%4,%5,%6,%7}, {%8,%9}, {%0,%1,%2,%3};"
        : "+f"(c[0]), "+f"(c[1]), "+f"(c[2]), "+f"(c[3])
        : "r"(a[0]), "r"(a[1]), "r"(a[2]), "r"(a[3]), "r"(b[0]), "r"(b[1]));
}

__device__ __forceinline__ float gelu_tanh(float v) {
    float u = 0.7978845608028654f * (v + 0.044715f * v * v * v);
    return 0.5f * v * (1.0f + tanhf(u));
}

// ---------------- merged prep: LN + rope table + weight convert ------------
__global__ void prep_all(const float* __restrict__ x,
                         const float* __restrict__ scale,
                         const float* __restrict__ offset,
                         const float* __restrict__ wq, const float* __restrict__ wk,
                         const float* __restrict__ wv, const float* __restrict__ wo,
                         const float* __restrict__ w1, const float* __restrict__ w2,
                         __half* __restrict__ xn, float2* __restrict__ rope,
                         __half* __restrict__ wqh, __half* __restrict__ wkh,
                         __half* __restrict__ wvh, __half* __restrict__ woh,
                         __half* __restrict__ w1h, __half* __restrict__ w2h) {
    int b = blockIdx.x, tid = threadIdx.x;
    __shared__ float red[256];
    if (b < TT) {
        const float* xr = x + (size_t)b * DD;
        float vals[8];
        float s = 0.f;
#pragma unroll
        for (int i = 0; i < 8; i++) { vals[i] = xr[tid + i * 256]; s += vals[i]; }
        red[tid] = s; __syncthreads();
#pragma unroll
        for (int off = 128; off > 0; off >>= 1) {
            if (tid < off) red[tid] += red[tid + off];
            __syncthreads();
        }
        float mean = red[0] * (1.0f / DD);
        __syncthreads();
        float vs = 0.f;
#pragma unroll
        for (int i = 0; i < 8; i++) { float d = vals[i] - mean; vs += d * d; }
        red[tid] = vs; __syncthreads();
#pragma unroll
        for (int off = 128; off > 0; off >>= 1) {
            if (tid < off) red[tid] += red[tid + off];
            __syncthreads();
        }
        float var = red[0] * (1.0f / DD);
        float inv = rsqrtf(var + 1e-5f);
#pragma unroll
        for (int i = 0; i < 8; i++) {
            int c = tid + i * 256;
            float y = scale[c] * inv * (vals[i] - mean) + offset[c];
            xn[(size_t)b * DD + c] = __float2half(y);
        }
    } else if (b < TT + 256) {
        int idx = (b - TT) * 256 + tid;
        int j = idx & 31, t = idx >> 5;
        float inv = (float)pow(10000.0, -(double)(2 * j) / 64.0);
        float ang = (float)t * inv;
        rope[idx] = make_float2(cosf(ang), sinf(ang));
    } else {
        const long long NV = 12LL * 1024 * 1024;
        long long stride = 1536LL * 256;
        for (long long i = (long long)(b - TT - 256) * 256 + tid;
             i < NV; i += stride) {
            const float* src; __half* dst; long long l;
            if (i < 4LL * 1024 * 1024) {
                int seg = (int)(i >> 20);
                l = i & 0xFFFFF;
                src = seg == 0 ? wq : (seg == 1 ? wk : (seg == 2 ? wv : wo));
                dst = seg == 0 ? wqh : (seg == 1 ? wkh : (seg == 2 ? wvh : woh));
            } else if (i < 8LL * 1024 * 1024) {
                l = i - 4LL * 1024 * 1024; src = w1; dst = w1h;
            } else {
                l = i - 8LL * 1024 * 1024; src = w2; dst = w2h;
            }
            float4 v = ((const float4*)src)[l];
            uint2 o;
            o.x = h2_as_u32(__floats2half2_rn(v.x, v.y));
            o.y = h2_as_u32(__floats2half2_rn(v.z, v.w));
            ((uint2*)dst)[l] = o;
        }
    }
}

// ---------------- HMMA GEMM: 128x128 tile, 8 warps (64x32/warp), K64 -------
// (proven R13/R14 shape: 256 thr, 2 CTA/SM, 3-stage, 122 regs)
// mode 1: outH0 = fp16(gelu(D + bias))                       (FF1)
// mode 7: merged QKV — blockIdx.x>>4 selects rope/rope/plain
// mode 9: WO+FF2 concat-K: chunks 0..31 = ctx@woh, 32..159 = ffh@w2h;
//         epilogue outF = D + res(x) + bias(b2)
#define ARB 144
#define BRB 272
#define ATILEB (128 * ARB)
#define BTILEB (64 * BRB)
#define STAGEB (ATILEB + BTILEB)
#define NSTAGE 3
#define GSMEM (NSTAGE * STAGEB)

__global__ void __launch_bounds__(256, 2) gemm_hmma(
    const __half* __restrict__ A,
    const __half* __restrict__ B0, const __half* __restrict__ B1,
    const __half* __restrict__ B2,
    int M, int N, int K,
    float* __restrict__ outF,
    __half* __restrict__ outH0, __half* __restrict__ outH1,
    __half* __restrict__ outH2,
    const float* __restrict__ bias, const float* __restrict__ res,
    const float2* __restrict__ rope, int mode) {
    extern __shared__ char smem[];
    const uint32_t sb = smem_u32(smem);

    const int tid = threadIdx.x;
    const int wid = tid >> 5, lane = tid & 31;
    const int wm = wid >> 2, wn = wid & 3;

    int bx = blockIdx.x;
    const __half* Bsel = B0;
    __half* outH = outH0;
    int em = mode;
    const int NN = N;
    if (mode == 7) {
        int which = bx >> 4;
        bx &= 15;
        Bsel = which == 0 ? B0 : (which == 1 ? B1 : B2);
        outH = which == 0 ? outH0 : (which == 1 ? outH1 : outH2);
        em   = which < 2 ? 4 : 6;
    }
    const int m0 = blockIdx.y << 7, n0 = bx << 7;

    const int cr = tid >> 2, cq = tid & 3;
    const int br = tid >> 3;
    const int bcq = (tid & 7) * 32;

    const uint32_t a_off = (uint32_t)(wm * 64 + (lane & 15)) * ARB + ((lane >> 4) << 4);
    const uint32_t b_toff = (uint32_t)((lane & 7) + ((lane >> 3) & 1) * 8) * BRB
                          + (uint32_t)(wn * 64) + (((lane >> 3) >> 1) << 4);

    float acc[4][4][4];
#pragma unroll
    for (int i = 0; i < 4; i++)
#pragma unroll
        for (int j = 0; j < 4; j++)
#pragma unroll
            for (int r = 0; r < 4; r++) acc[i][j][r] = 0.f;

    const int nch = (mode == 9) ? ((DD + FFD) >> 6) : (K >> 6);
    const __half* Ab0 = A + (size_t)(m0 + cr) * K + cq * 16;
    const __half* Ab1 = Ab0 + (size_t)64 * K;
    const __half* Bb0 = Bsel + (size_t)br * NN + n0 + bcq / 2;
    const __half* Bb1 = Bb0 + (size_t)32 * NN;

#define PREFETCH_G(ci) do {                                                   \
        if ((ci) < nch) {                                                     \
            const uint32_t st = sb + ((ci) % NSTAGE) * STAGEB;                \
            int kc = (ci) << 6;                                               \
            cpa16(st + cr * ARB + cq * 32,              Ab0 + kc);            \
            cpa16(st + cr * ARB + cq * 32 + 16,         Ab0 + kc + 8);        \
            cpa16(st + (cr + 64) * ARB + cq * 32,       Ab1 + kc);            \
            cpa16(st + (cr + 64) * ARB + cq * 32 + 16,  Ab1 + kc + 8);        \
            size_t bk = (size_t)kc * NN;                                      \
            cpa16(st + ATILEB + br * BRB + bcq,             Bb0 + bk);        \
            cpa16(st + ATILEB + br * BRB + bcq + 16,        Bb0 + bk + 8);    \
            cpa16(st + ATILEB + (br + 32) * BRB + bcq,      Bb1 + bk);        \
            cpa16(st + ATILEB + (br + 32) * BRB + bcq + 16, Bb1 + bk + 8);    \
        }                                                                     \
        CPA_COMMIT();                                                         \
    } while (0)

    PREFETCH_G(0);
    PREFETCH_G(1);

    for (int i = 0; i < nch; i++) {
        CPA_WAIT1();
        __syncthreads();
        if (mode == 9 && i + 2 == (DD >> 6)) {
            Ab0 = g_ffh + (size_t)(m0 + cr) * FFD + cq * 16 - DD;
            Ab1 = Ab0 + (size_t)64 * FFD;
            Bb0 = g_w2h + (size_t)br * DD + (n0 + bcq / 2) - (size_t)DD * DD;
            Bb1 = Bb0 + (size_t)32 * DD;
        }
        PREFETCH_G(i + 2);

        const uint32_t sA = sb + (i % NSTAGE) * STAGEB;
        const uint32_t sB = sA + ATILEB;
#pragma unroll
        for (int ks = 0; ks < 4; ks++) {
            uint32_t a[4][4];
#pragma unroll
            for (int fi = 0; fi < 4; fi++)
                ldsm4(a[fi][0], a[fi][1], a[fi][2], a[fi][3],
                      sA + a_off + fi * 16 * ARB + ks * 32);
            uint32_t b[4][2];
#pragma unroll
            for (int j2 = 0; j2 < 2; j2++) {
                uint32_t r0, r1, r2, r3;
                ldsm4t(r0, r1, r2, r3,
                       sB + b_toff + ks * 16 * BRB + j2 * 32);
                b[j2 * 2][0] = r0; b[j2 * 2][1] = r1;
                b[j2 * 2 + 1][0] = r2; b[j2 * 2 + 1][1] = r3;
            }
#pragma unroll
            for (int fi = 0; fi < 4; fi++)
#pragma unroll
                for (int j = 0; j < 4; j++)
                    mma16816(acc[fi][j], a[fi], b[j]);
        }
    }
#undef PREFETCH_G

    const int r_base = m0 + wm * 64 + (lane >> 2);
    const int c_base = n0 + wn * 32 + (lane & 3) * 2;
#pragma unroll
    for (int fi = 0; fi < 4; fi++) {
#pragma unroll
        for (int j = 0; j < 4; j++) {
            int col = c_base + j * 8;
#pragma unroll
            for (int half_ = 0; half_ < 2; half_++) {
                int r = r_base + fi * 16 + half_ * 8;
                float v0 = acc[fi][j][half_ * 2 + 0];
                float v1 = acc[fi][j][half_ * 2 + 1];
                size_t o = (size_t)r * NN + col;
                if (em == 1) {
                    *(__half2*)&outH[o] = __floats2half2_rn(
                        gelu_tanh(v0 + bias[col]), gelu_tanh(v1 + bias[col + 1]));
                } else if (em == 4) {
                    int hcol = col & 127;
                    if (hcol < 64) {
                        float2 cs = rope[r * 32 + (hcol >> 1)];
                        *(__half2*)&outH[o] = __floats2half2_rn(
                            v0 * cs.x - v1 * cs.y, v1 * cs.x + v0 * cs.y);
                    } else {
                        *(__half2*)&outH[o] = __floats2half2_rn(v0, v1);
                    }
                } else if (em == 6) {
                    *(__half2*)&outH[o] = __floats2half2_rn(v0, v1);
                } else {  // em == 9: out = acc + x + b2
                    float2 rr = *(const float2*)&res[o];
                    float2 ov = make_float2(v0 + rr.x + bias[col],
                                            v1 + rr.y + bias[col + 1]);
                    *(float2*)&outF[o] = ov;
                }
            }
        }
    }
}

// ---------------- Flash attention: Br=64, 4 warps, 2 CTA/SM, 3-stage KV ----
#define KRB 272
#define KSTG (64 * KRB)
#define SSTG (2 * KSTG)               // 34816 per stage (K + V)
#define ANSTG 3
#define ASMEM (ANSTG * SSTG)          // 104448

__global__ void __launch_bounds__(128, 2) attn_mma(
    const __half* __restrict__ qh, const __half* __restrict__ kh,
    const __half* __restrict__ vh, __half* __restrict__ ctx) {
    extern __shared__ char smem[];
    const uint32_t sb = smem_u32(smem);
    const int tid = threadIdx.x, w = tid >> 5, lane = tid & 31;
    const int qt = gridDim.x - 1 - blockIdx.x;     // LPT: longest first
    const int h = blockIdx.y;
    const int q0 = qt * 64;
    const int hbase = h * DHD;
    const int nkt = qt + 1;

    // ---- load Q tile [64][128] into smem (stage-0 area), extract A-frags ---
#pragma unroll
    for (int p = 0; p < 8; p++) {
        int idx = tid + p * 128;
        int row = idx >> 4, c = idx & 15;
        cpa16(sb + row * KRB + c * 16,
              qh + (size_t)(q0 + row) * DD + hbase + c * 8);
    }
    CPA_COMMIT(); CPA_WAIT0(); __syncthreads();
    uint32_t qf[8][4];
    {
        uint32_t aoff = (uint32_t)(w * 16 + (lane & 15)) * KRB + ((lane >> 4) << 4);
#pragma unroll
        for (int ks = 0; ks < 8; ks++)
            ldsm4(qf[ks][0], qf[ks][1], qf[ks][2], qf[ks][3],
                  sb + aoff + ks * 32);
    }
    __syncthreads();

    float O[16][4];
#pragma unroll
    for (int j = 0; j < 16; j++)
#pragma unroll
        for (int r = 0; r < 4; r++) O[j][r] = 0.f;
    float m0 = -1e30f, m1 = -1e30f, l0 = 0.f, l1 = 0.f;

    // guarded loader: ALWAYS commits (uniform group accounting)
#define LOADKV_G(kt_) do {                                                    \
        if ((kt_) < nkt) {                                                    \
            int kv0 = (kt_) * 64;                                             \
            uint32_t base = sb + ((kt_) % ANSTG) * SSTG;                      \
            _Pragma("unroll")                                                 \
            for (int p = 0; p < 8; p++) {                                     \
                int idx = tid + p * 128;                                      \
                int row = idx >> 4, c = idx & 15;                             \
                cpa16(base + row * KRB + c * 16,                              \
                      kh + (size_t)(kv0 + row) * DD + hbase + c * 8);         \
            }                                                                 \
            _Pragma("unroll")                                                 \
            for (int p = 0; p < 8; p++) {                                     \
                int idx = tid + p * 128;                                      \
                int row = idx >> 4, c = idx & 15;                             \
                cpa16(base + KSTG + row * KRB + c * 16,                       \
                      vh + (size_t)(kv0 + row) * DD + hbase + c * 8);         \
            }                                                                 \
        }                                                                     \
        CPA_COMMIT();                                                         \
    } while (0)

    LOADKV_G(0);
    LOADKV_G(1);

    const float sm_scale = 0.08838834764831845f;
    const int r0g = q0 + w * 16 + (lane >> 2);

    for (int kt = 0; kt < nkt; kt++) {
        CPA_WAIT1();              // chunk kt landed (chunk kt+1 may pend)
        __syncthreads();          // all warps done with stage (kt-1)%3
        LOADKV_G(kt + 2);         // overwrites stage (kt+2)%3 = (kt-1)%3 — safe

        const uint32_t cur = sb + (kt % ANSTG) * SSTG;

        // ---- S = Q K^T ----
        float S[8][4];
#pragma unroll
        for (int j = 0; j < 8; j++)
#pragma unroll
            for (int r = 0; r < 4; r++) S[j][r] = 0.f;
        {
            uint32_t bko = (uint32_t)((lane & 7) + ((lane >> 4) << 3)) * KRB
                         + (((lane >> 3) & 1) << 4);
#pragma unroll
            for (int j2 = 0; j2 < 4; j2++) {
                uint32_t bbase = cur + bko + j2 * 16 * KRB;
#pragma unroll
                for (int ks = 0; ks < 8; ks++) {
                    uint32_t r0, r1, r2, r3;
                    ldsm4(r0, r1, r2, r3, bbase + ks * 32);
                    uint32_t bb0[2] = {r0, r1};
                    mma16816(S[2 * j2], qf[ks], bb0);
                    uint32_t bb1[2] = {r2, r3};
                    mma16816(S[2 * j2 + 1], qf[ks], bb1);
                }
            }
        }

        // ---- scale + causal mask (diagonal tile only) ----
        int kv0 = kt * 64;
        bool msk = (kt == nkt - 1);
#pragma unroll
        for (int j = 0; j < 8; j++) {
            S[j][0] *= sm_scale; S[j][1] *= sm_scale;
            S[j][2] *= sm_scale; S[j][3] *= sm_scale;
            if (msk) {
                int c0 = kv0 + j * 8 + 2 * (lane & 3);
                if (c0 > r0g)     S[j][0] = -1e9f;
                if (c0 + 1 > r0g) S[j][1] = -1e9f;
                if (c0 > r0g + 8)     S[j][2] = -1e9f;
                if (c0 + 1 > r0g + 8) S[j][3] = -1e9f;
            }
        }

        // ---- online softmax ----
        float mx0 = -1e30f, mx1 = -1e30f;
#pragma unroll
        for (int j = 0; j < 8; j++) {
            mx0 = fmaxf(mx0, fmaxf(S[j][0], S[j][1]));
            mx1 = fmaxf(mx1, fmaxf(S[j][2], S[j][3]));
        }
        mx0 = fmaxf(mx0, __shfl_xor_sync(0xffffffffu, mx0, 1));
        mx0 = fmaxf(mx0, __shfl_xor_sync(0xffffffffu, mx0, 2));
        mx1 = fmaxf(mx1, __shfl_xor_sync(0xffffffffu, mx1, 1));
        mx1 = fmaxf(mx1, __shfl_xor_sync(0xffffffffu, mx1, 2));
        float m0n = fmaxf(m0, mx0), m1n = fmaxf(m1, mx1);
        float c0f = __expf(m0 - m0n), c1f = __expf(m1 - m1n);
        float s0 = 0.f, s1 = 0.f;
#pragma unroll
        for (int j = 0; j < 8; j++) {
            S[j][0] = __expf(S[j][0] - m0n);
            S[j][1] = __expf(S[j][1] - m0n);
            S[j][2] = __expf(S[j][2] - m1n);
            S[j][3] = __expf(S[j][3] - m1n);
            s0 += S[j][0] + S[j][1];
            s1 += S[j][2] + S[j][3];
        }
        s0 += __shfl_xor_sync(0xffffffffu, s0, 1);
        s0 += __shfl_xor_sync(0xffffffffu, s0, 2);
        s1 += __shfl_xor_sync(0xffffffffu, s1, 1);
        s1 += __shfl_xor_sync(0xffffffffu, s1, 2);
        l0 = l0 * c0f + s0;
        l1 = l1 * c1f + s1;
        m0 = m0n; m1 = m1n;
#pragma unroll
        for (int j = 0; j < 16; j++) {
            O[j][0] *= c0f; O[j][1] *= c0f;
            O[j][2] *= c1f; O[j][3] *= c1f;
        }

        // ---- O += P V ----
        {
            uint32_t vbase = cur + KSTG;
            uint32_t bvo = (uint32_t)((lane & 7) + ((lane >> 3) & 1) * 8) * KRB
                         + (((lane >> 3) >> 1) << 4);
#pragma unroll
            for (int kk = 0; kk < 4; kk++) {
                uint32_t pf[4];
                pf[0] = h2_as_u32(__floats2half2_rn(S[2 * kk][0], S[2 * kk][1]));
                pf[1] = h2_as_u32(__floats2half2_rn(S[2 * kk][2], S[2 * kk][3]));
                pf[2] = h2_as_u32(__floats2half2_rn(S[2 * kk + 1][0], S[2 * kk + 1][1]));
                pf[3] = h2_as_u32(__floats2half2_rn(S[2 * kk + 1][2], S[2 * kk + 1][3]));
#pragma unroll
                for (int j2 = 0; j2 < 8; j2++) {
                    uint32_t r0, r1, r2, r3;
                    ldsm4t(r0, r1, r2, r3,
                           vbase + bvo + kk * 16 * KRB + j2 * 32);
                    uint32_t bb0[2] = {r0, r1};
                    mma16816(O[2 * j2], pf, bb0);
                    uint32_t bb1[2] = {r2, r3};
                    mma16816(O[2 * j2 + 1], pf, bb1);
                }
            }
        }
        __syncthreads();
    }
#undef LOADKV_G

    // ---- epilogue ----
    float i0 = 1.f / l0, i1 = 1.f / l1;
    int row0 = q0 + w * 16 + (lane >> 2);
#pragma unroll
    for (int j = 0; j < 16; j++) {
        int col = hbase + j * 8 + 2 * (lane & 3);
        *(__half2*)(ctx + (size_t)row0 * DD + col) =
            __floats2half2_rn(O[j][0] * i0, O[j][1] * i0);
        *(__half2*)(ctx + (size_t)(row0 + 8) * DD + col) =
            __floats2half2_rn(O[j][2] * i1, O[j][3] * i1);
    }
}

// ---------------- launch ----------------------------------------------------
extern "C" void kernel_launch(void* const* d_in, const int* in_sizes, int n_in,
                              void* d_out, int out_size) {
    const float* x      = (const float*)d_in[0];
    const float* scale  = (const float*)d_in[2];
    const float* offset = (const float*)d_in[3];
    const float* wq     = (const float*)d_in[4];
    const float* wk     = (const float*)d_in[5];
    const float* wv     = (const float*)d_in[6];
    const float* wo     = (const float*)d_in[7];
    const float* w1     = (const float*)d_in[8];
    const float* b1     = (const float*)d_in[9];
    const float* w2     = (const float*)d_in[10];
    const float* b2     = (const float*)d_in[11];
    float* out = (float*)d_out;

    __half *xn, *ctx, *ffh, *wqh, *wkh, *wvh, *woh, *w1h, *w2h, *qh, *kh, *vh;
    float2* rope;
    cudaGetSymbolAddress((void**)&xn, g_xn);
    cudaGetSymbolAddress((void**)&qh, g_qh);
    cudaGetSymbolAddress((void**)&kh, g_kh);
    cudaGetSymbolAddress((void**)&vh, g_vh);
    cudaGetSymbolAddress((void**)&ctx, g_ctx);
    cudaGetSymbolAddress((void**)&ffh, g_ffh);
    cudaGetSymbolAddress((void**)&wqh, g_wqh);
    cudaGetSymbolAddress((void**)&wkh, g_wkh);
    cudaGetSymbolAddress((void**)&wvh, g_wvh);
    cudaGetSymbolAddress((void**)&woh, g_woh);
    cudaGetSymbolAddress((void**)&w1h, g_w1h);
    cudaGetSymbolAddress((void**)&w2h, g_w2h);
    cudaGetSymbolAddress((void**)&rope, g_rope);

    static cudaStream_t s2 = nullptr;
    static cudaEvent_t evPrep = nullptr, evFF1 = nullptr;
    if (s2 == nullptr) {
        cudaStreamCreateWithFlags(&s2, cudaStreamNonBlocking);
        cudaEventCreateWithFlags(&evPrep, cudaEventDisableTiming);
        cudaEventCreateWithFlags(&evFF1, cudaEventDisableTiming);
    }

    cudaFuncSetAttribute(attn_mma,
                         cudaFuncAttributeMaxDynamicSharedMemorySize, ASMEM);
    cudaFuncSetAttribute(gemm_hmma,
                         cudaFuncAttributeMaxDynamicSharedMemorySize, GSMEM);

    // prep (LN + rope + convert) on main stream
    prep_all<<<3840, 256>>>(x, scale, offset, wq, wk, wv, wo, w1, w2,
                            xn, rope, wqh, wkh, wvh, woh, w1h, w2h);
    cudaEventRecord(evPrep, 0);

    // FF1 on side stream (depends only on prep)
    cudaStreamWaitEvent(s2, evPrep, 0);
    gemm_hmma<<<dim3(FFD / 128, TT / 128), 256, GSMEM, s2>>>(
        xn, w1h, nullptr, nullptr, TT, FFD, DD,
        nullptr, ffh, nullptr, nullptr, b1, nullptr, nullptr, 1);
    cudaEventRecord(evFF1, s2);

    // QKV + attention on main stream (concurrent with FF1)
    gemm_hmma<<<dim3(48, TT / 128), 256, GSMEM>>>(
        xn, wqh, wkh, wvh, TT, DD, DD,
        nullptr, qh, kh, vh, nullptr, nullptr, rope, 7);
    attn_mma<<<dim3(TT / 64, HH), 128, ASMEM>>>(qh, kh, vh, ctx);

    // join, then fused WO + FF2 (concatenated K): out = ctx@wo + ffh@w2 + x + b2
    cudaStreamWaitEvent(0, evFF1, 0);
    gemm_hmma<<<dim3(DD / 128, TT / 128), 256, GSMEM>>>(
        ctx, woh, nullptr, nullptr, TT, DD, DD,
        out, nullptr, nullptr, nullptr, b2, x, nullptr, 9);
}